// round 1
// baseline (speedup 1.0000x reference)
#include <cuda_runtime.h>
#include <math.h>
#include <stdint.h>

// ---------------------------------------------------------------------------
// Problem dims (fixed by the dataset)
//   D=512 (input dim), K=8 (bilinear slices), L=64 (hash len),
//   Q=4096 (queries), C=4096 (classes)
// Pipeline:
//   T[c, j*8+k]   = sum_i class[c,i] * M[i,j,k]             (GEMM 4096x4096x512)
//   other[q,c]    = b + sum_k w_k * relu(sum_j query[q,j]*T[c,j,k])   (fused)
//   scores        = softmax_rows(other)
//   qf[q,:]       = scores[q,:] @ class + query[q,:]        (GEMM 4096x512x4096)
//   out[q,l]      = tanh(qf[q,:] . hash_w[l,:] + hash_b[l]) (GEMM 4096x64x512)
// ---------------------------------------------------------------------------

__device__ float g_T[(size_t)4096 * 4096];      // 64 MB scratch: [c][(j*8+k)]
__device__ float g_other[(size_t)4096 * 4096];  // 64 MB scratch: [q][c]
__device__ float g_qf[(size_t)4096 * 512];      // 8 MB scratch:  [q][d]
__device__ float g_hwT[512 * 64];               // hash_w transposed [d][l]

// ---------------------------------------------------------------------------
// Generic tiled fp32 GEMM: out[M,N] = A[M,K] @ B[K,N]  (+ epilogue)
//   EPI=0: plain store
//   EPI=1: out = acc + X[r*N+c]        (residual add, X is [M,N])
//   EPI=2: out = tanh(acc + X[c])      (bias + tanh, X is [N])
// ---------------------------------------------------------------------------
template <int BM, int BN, int BK, int TM, int TN, int EPI>
__global__ void __launch_bounds__((BM / TM) * (BN / TN), 2)
gemm_f32(const float* __restrict__ A, const float* __restrict__ B,
         const float* __restrict__ X, float* __restrict__ out,
         int M, int N, int K)
{
    constexpr int THREADS = (BM / TM) * (BN / TN);
    __shared__ float As[BK][BM + 4];  // [k][m] (transposed for vector reads)
    __shared__ float Bs[BK][BN + 4];  // [k][n]

    const int bm = blockIdx.y * BM;
    const int bn = blockIdx.x * BN;
    const int tid = threadIdx.x;
    const int tcol = tid % (BN / TN);
    const int trow = tid / (BN / TN);

    float acc[TM][TN];
#pragma unroll
    for (int i = 0; i < TM; i++)
#pragma unroll
        for (int j = 0; j < TN; j++) acc[i][j] = 0.0f;

    for (int k0 = 0; k0 < K; k0 += BK) {
        // Load A tile (BM x BK) as float4s, store transposed into As
#pragma unroll
        for (int it = 0; it < (BM * BK / 4) / THREADS; it++) {
            int i = tid + it * THREADS;
            int r = i / (BK / 4);
            int c4 = (i % (BK / 4)) * 4;
            float4 v = *(const float4*)(A + (size_t)(bm + r) * K + k0 + c4);
            As[c4 + 0][r] = v.x;
            As[c4 + 1][r] = v.y;
            As[c4 + 2][r] = v.z;
            As[c4 + 3][r] = v.w;
        }
        // Load B tile (BK x BN) as float4s
#pragma unroll
        for (int it = 0; it < (BK * BN / 4) / THREADS; it++) {
            int i = tid + it * THREADS;
            int r = i / (BN / 4);
            int c4 = (i % (BN / 4)) * 4;
            *(float4*)&Bs[r][c4] = *(const float4*)(B + (size_t)(k0 + r) * N + bn + c4);
        }
        __syncthreads();

#pragma unroll
        for (int kk = 0; kk < BK; kk++) {
            float af[TM], bf[TN];
#pragma unroll
            for (int i = 0; i < TM; i += 4) {
                float4 v = *(const float4*)&As[kk][trow * TM + i];
                af[i] = v.x; af[i + 1] = v.y; af[i + 2] = v.z; af[i + 3] = v.w;
            }
#pragma unroll
            for (int j = 0; j < TN; j += 4) {
                float4 v = *(const float4*)&Bs[kk][tcol * TN + j];
                bf[j] = v.x; bf[j + 1] = v.y; bf[j + 2] = v.z; bf[j + 3] = v.w;
            }
#pragma unroll
            for (int i = 0; i < TM; i++)
#pragma unroll
                for (int j = 0; j < TN; j++)
                    acc[i][j] = fmaf(af[i], bf[j], acc[i][j]);
        }
        __syncthreads();
    }

#pragma unroll
    for (int i = 0; i < TM; i++) {
        int r = bm + trow * TM + i;
#pragma unroll
        for (int j = 0; j < TN; j++) {
            int c = bn + tcol * TN + j;
            float v = acc[i][j];
            if (EPI == 1) v += X[(size_t)r * N + c];
            else if (EPI == 2) v = tanhf(v + X[c]);
            out[(size_t)r * N + c] = v;
        }
    }
}

// ---------------------------------------------------------------------------
// Fused bilinear + relu + score kernel (the 137 GFLOP stage):
//   other[q,c] = score_b + sum_k score_w[k] * relu( sum_d query[q,d]*T[c, d*8+k] )
// Tile: 128 q x 16 c x (all 8 k), BK(d)=32, 256 threads.
// Thread: 8 q x 1 c x 8 k = 64 accumulators.
// ---------------------------------------------------------------------------
__global__ void __launch_bounds__(256, 2)
bilinear_score_kernel(const float* __restrict__ query,  // [4096,512]
                      const float* __restrict__ T,      // [4096,4096] = [c][(d*8+k)]
                      const float* __restrict__ score_w,// [8]
                      const float* __restrict__ score_b,// [1]
                      float* __restrict__ other)        // [4096,4096]
{
    __shared__ float As[32][128 + 4];  // [d][q]
    __shared__ float Bs[32][128 + 4];  // [d][c*8+k]  (16 classes * 8 k)

    const int q0 = blockIdx.y * 128;
    const int c0 = blockIdx.x * 16;
    const int tid = threadIdx.x;
    const int cidx = tid & 15;  // class within tile
    const int qg = tid >> 4;    // query group (8 queries each)

    float acc[8][8];  // [qi][k]
#pragma unroll
    for (int i = 0; i < 8; i++)
#pragma unroll
        for (int k = 0; k < 8; k++) acc[i][k] = 0.0f;

    for (int d0 = 0; d0 < 512; d0 += 32) {
        // A tile: 128 q x 32 d  (1024 float4, 4 per thread), store as [d][q]
#pragma unroll
        for (int it = 0; it < 4; it++) {
            int i4 = tid + it * 256;
            int q = i4 >> 3;
            int dd = (i4 & 7) * 4;
            float4 v = *(const float4*)(query + (size_t)(q0 + q) * 512 + d0 + dd);
            As[dd + 0][q] = v.x;
            As[dd + 1][q] = v.y;
            As[dd + 2][q] = v.z;
            As[dd + 3][q] = v.w;
        }
        // B tile: 16 c x 32 d x 8 k. Per class the chunk T[(c0+c)*4096 + d0*8 .. +256)
        // is contiguous; store as Bs[d][c*8+k].
#pragma unroll
        for (int it = 0; it < 4; it++) {
            int i4 = tid + it * 256;
            int c = i4 >> 6;            // 0..15
            int rem = (i4 & 63) * 4;    // float position within 256-chunk
            int dl = rem >> 3;          // 0..31
            int kk = rem & 7;           // 0 or 4
            float4 v = *(const float4*)(T + (size_t)(c0 + c) * 4096 + d0 * 8 + rem);
            *(float4*)&Bs[dl][c * 8 + kk] = v;
        }
        __syncthreads();

#pragma unroll 8
        for (int dd = 0; dd < 32; dd++) {
            float4 b0 = *(const float4*)&Bs[dd][cidx * 8];
            float4 b1 = *(const float4*)&Bs[dd][cidx * 8 + 4];
            float4 a0 = *(const float4*)&As[dd][qg * 8];
            float4 a1 = *(const float4*)&As[dd][qg * 8 + 4];
            float a[8] = {a0.x, a0.y, a0.z, a0.w, a1.x, a1.y, a1.z, a1.w};
#pragma unroll
            for (int i = 0; i < 8; i++) {
                acc[i][0] = fmaf(a[i], b0.x, acc[i][0]);
                acc[i][1] = fmaf(a[i], b0.y, acc[i][1]);
                acc[i][2] = fmaf(a[i], b0.z, acc[i][2]);
                acc[i][3] = fmaf(a[i], b0.w, acc[i][3]);
                acc[i][4] = fmaf(a[i], b1.x, acc[i][4]);
                acc[i][5] = fmaf(a[i], b1.y, acc[i][5]);
                acc[i][6] = fmaf(a[i], b1.z, acc[i][6]);
                acc[i][7] = fmaf(a[i], b1.w, acc[i][7]);
            }
        }
        __syncthreads();
    }

    // Epilogue: relu -> weighted sum over k -> store
    float w[8];
#pragma unroll
    for (int k = 0; k < 8; k++) w[k] = score_w[k];
    float sb = score_b[0];

#pragma unroll
    for (int i = 0; i < 8; i++) {
        float s = sb;
#pragma unroll
        for (int k = 0; k < 8; k++) s = fmaf(fmaxf(acc[i][k], 0.0f), w[k], s);
        other[(size_t)(q0 + qg * 8 + i) * 4096 + c0 + cidx] = s;
    }
}

// ---------------------------------------------------------------------------
// Row softmax, in place, one block (256 threads) per row of 4096.
// ---------------------------------------------------------------------------
__global__ void softmax_rows(float* __restrict__ o)
{
    const int row = blockIdx.x;
    float* p = o + (size_t)row * 4096;
    const int tid = threadIdx.x;

    float v[16];
    float mx = -1e30f;
#pragma unroll
    for (int i = 0; i < 16; i++) {
        v[i] = p[tid + (i << 8)];
        mx = fmaxf(mx, v[i]);
    }

    __shared__ float sm[8];
#pragma unroll
    for (int o2 = 16; o2 > 0; o2 >>= 1)
        mx = fmaxf(mx, __shfl_xor_sync(0xffffffffu, mx, o2));
    if ((tid & 31) == 0) sm[tid >> 5] = mx;
    __syncthreads();
    mx = sm[0];
#pragma unroll
    for (int i = 1; i < 8; i++) mx = fmaxf(mx, sm[i]);
    __syncthreads();

    float s = 0.0f;
#pragma unroll
    for (int i = 0; i < 16; i++) {
        v[i] = expf(v[i] - mx);
        s += v[i];
    }
#pragma unroll
    for (int o2 = 16; o2 > 0; o2 >>= 1)
        s += __shfl_xor_sync(0xffffffffu, s, o2);
    if ((tid & 31) == 0) sm[tid >> 5] = s;
    __syncthreads();
    s = 0.0f;
#pragma unroll
    for (int i = 0; i < 8; i++) s += sm[i];

    float inv = 1.0f / s;
#pragma unroll
    for (int i = 0; i < 16; i++) p[tid + (i << 8)] = v[i] * inv;
}

// ---------------------------------------------------------------------------
// Transpose hash_w [64,512] -> g_hwT [512,64]
// ---------------------------------------------------------------------------
__global__ void transpose_hw(const float* __restrict__ hw)
{
    int idx = blockIdx.x * blockDim.x + threadIdx.x;  // 0..32767
    int l = idx >> 9;
    int d = idx & 511;
    g_hwT[d * 64 + l] = hw[idx];
}

// ---------------------------------------------------------------------------
extern "C" void kernel_launch(void* const* d_in, const int* in_sizes, int n_in,
                              void* d_out, int out_size)
{
    const float* class_v = (const float*)d_in[0];  // [4096,512]
    const float* query_v = (const float*)d_in[1];  // [4096,512]
    const float* Mmat    = (const float*)d_in[2];  // [512,512,8] == [i][(j,k)]
    const float* score_w = (const float*)d_in[3];  // [8]
    const float* score_b = (const float*)d_in[4];  // [1]
    const float* hash_w  = (const float*)d_in[5];  // [64,512]
    const float* hash_b  = (const float*)d_in[6];  // [64]
    float* out = (float*)d_out;                    // [4096,64]

    float *T, *other, *qf, *hwT;
    cudaGetSymbolAddress((void**)&T, g_T);
    cudaGetSymbolAddress((void**)&other, g_other);
    cudaGetSymbolAddress((void**)&qf, g_qf);
    cudaGetSymbolAddress((void**)&hwT, g_hwT);

    // Stage 0: transpose hash_w (tiny)
    transpose_hw<<<128, 256>>>(hash_w);

    // Stage 1: T = class @ M_reshaped   [4096 x 4096, K=512]
    gemm_f32<128, 128, 16, 8, 8, 0><<<dim3(32, 32), 256>>>(
        class_v, Mmat, nullptr, T, 4096, 4096, 512);

    // Stage 2: fused bilinear + relu + score -> other [4096 x 4096]
    bilinear_score_kernel<<<dim3(256, 32), 256>>>(query_v, T, score_w, score_b, other);

    // Stage 3: softmax over class dim (in place)
    softmax_rows<<<4096, 256>>>(other);

    // Stage 4: qf = scores @ class + query   [4096 x 512, K=4096]
    gemm_f32<128, 128, 16, 8, 8, 1><<<dim3(4, 32), 256>>>(
        other, class_v, query_v, qf, 4096, 512, 4096);

    // Stage 5: out = tanh(qf @ hwT + hash_b)   [4096 x 64, K=512]
    gemm_f32<64, 64, 16, 4, 4, 2><<<dim3(1, 64), 256>>>(
        qf, hwT, hash_b, out, 4096, 64, 512);
}

// round 2
// speedup vs baseline: 1.0015x; 1.0015x over previous
#include <cuda_runtime.h>
#include <math.h>
#include <stdint.h>

// ---------------------------------------------------------------------------
// Problem dims (fixed by the dataset)
//   D=512 (input dim), K=8 (bilinear slices), L=64 (hash len),
//   Q=4096 (queries), C=4096 (classes)
// Pipeline:
//   T[c, j*8+k]   = sum_i class[c,i] * M[i,j,k]             (GEMM 4096x4096x512)
//   other[q,c]    = b + sum_k w_k * relu(sum_j query[q,j]*T[c,j,k])   (fused)
//   scores        = softmax_rows(other)
//   qf[q,:]       = scores[q,:] @ class + query[q,:]        (GEMM 4096x512x4096)
//   out[q,l]      = tanh(qf[q,:] . hash_w[l,:] + hash_b[l]) (GEMM 4096x64x512)
// ---------------------------------------------------------------------------

__device__ float g_T[(size_t)4096 * 4096];      // 64 MB scratch: [c][(j*8+k)]
__device__ float g_other[(size_t)4096 * 4096];  // 64 MB scratch: [q][c]
__device__ float g_qf[(size_t)4096 * 512];      // 8 MB scratch:  [q][d]
__device__ float g_hwT[512 * 64];               // hash_w transposed [d][l]

// ---------------------------------------------------------------------------
// Generic tiled fp32 GEMM: out[M,N] = A[M,K] @ B[K,N]  (+ epilogue)
//   EPI=0: plain store
//   EPI=1: out = acc + X[r*N+c]        (residual add, X is [M,N])
//   EPI=2: out = tanh(acc + X[c])      (bias + tanh, X is [N])
// ---------------------------------------------------------------------------
template <int BM, int BN, int BK, int TM, int TN, int EPI>
__global__ void __launch_bounds__((BM / TM) * (BN / TN), 2)
gemm_f32(const float* __restrict__ A, const float* __restrict__ B,
         const float* __restrict__ X, float* __restrict__ out,
         int M, int N, int K)
{
    constexpr int THREADS = (BM / TM) * (BN / TN);
    __shared__ float As[BK][BM + 4];  // [k][m] (transposed for vector reads)
    __shared__ float Bs[BK][BN + 4];  // [k][n]

    const int bm = blockIdx.y * BM;
    const int bn = blockIdx.x * BN;
    const int tid = threadIdx.x;
    const int tcol = tid % (BN / TN);
    const int trow = tid / (BN / TN);

    float acc[TM][TN];
#pragma unroll
    for (int i = 0; i < TM; i++)
#pragma unroll
        for (int j = 0; j < TN; j++) acc[i][j] = 0.0f;

    for (int k0 = 0; k0 < K; k0 += BK) {
        // Load A tile (BM x BK) as float4s, store transposed into As
#pragma unroll
        for (int it = 0; it < (BM * BK / 4) / THREADS; it++) {
            int i = tid + it * THREADS;
            int r = i / (BK / 4);
            int c4 = (i % (BK / 4)) * 4;
            float4 v = *(const float4*)(A + (size_t)(bm + r) * K + k0 + c4);
            As[c4 + 0][r] = v.x;
            As[c4 + 1][r] = v.y;
            As[c4 + 2][r] = v.z;
            As[c4 + 3][r] = v.w;
        }
        // Load B tile (BK x BN) as float4s
#pragma unroll
        for (int it = 0; it < (BK * BN / 4) / THREADS; it++) {
            int i = tid + it * THREADS;
            int r = i / (BN / 4);
            int c4 = (i % (BN / 4)) * 4;
            *(float4*)&Bs[r][c4] = *(const float4*)(B + (size_t)(k0 + r) * N + bn + c4);
        }
        __syncthreads();

#pragma unroll
        for (int kk = 0; kk < BK; kk++) {
            float af[TM], bf[TN];
#pragma unroll
            for (int i = 0; i < TM; i += 4) {
                float4 v = *(const float4*)&As[kk][trow * TM + i];
                af[i] = v.x; af[i + 1] = v.y; af[i + 2] = v.z; af[i + 3] = v.w;
            }
#pragma unroll
            for (int j = 0; j < TN; j += 4) {
                float4 v = *(const float4*)&Bs[kk][tcol * TN + j];
                bf[j] = v.x; bf[j + 1] = v.y; bf[j + 2] = v.z; bf[j + 3] = v.w;
            }
#pragma unroll
            for (int i = 0; i < TM; i++)
#pragma unroll
                for (int j = 0; j < TN; j++)
                    acc[i][j] = fmaf(af[i], bf[j], acc[i][j]);
        }
        __syncthreads();
    }

#pragma unroll
    for (int i = 0; i < TM; i++) {
        int r = bm + trow * TM + i;
#pragma unroll
        for (int j = 0; j < TN; j++) {
            int c = bn + tcol * TN + j;
            float v = acc[i][j];
            if (EPI == 1) v += X[(size_t)r * N + c];
            else if (EPI == 2) v = tanhf(v + X[c]);
            out[(size_t)r * N + c] = v;
        }
    }
}

// ---------------------------------------------------------------------------
// Fused bilinear + relu + score kernel (the 137 GFLOP stage):
//   other[q,c] = score_b + sum_k score_w[k] * relu( sum_d query[q,d]*T[c, d*8+k] )
// Tile: 128 q x 16 c x (all 8 k), BK(d)=32, 256 threads.
// Thread: 8 q x 1 c x 8 k = 64 accumulators.
// ---------------------------------------------------------------------------
__global__ void __launch_bounds__(256, 2)
bilinear_score_kernel(const float* __restrict__ query,  // [4096,512]
                      const float* __restrict__ T,      // [4096,4096] = [c][(d*8+k)]
                      const float* __restrict__ score_w,// [8]
                      const float* __restrict__ score_b,// [1]
                      float* __restrict__ other)        // [4096,4096]
{
    __shared__ float As[32][128 + 4];  // [d][q]
    __shared__ float Bs[32][128 + 4];  // [d][c*8+k]  (16 classes * 8 k)

    const int q0 = blockIdx.y * 128;
    const int c0 = blockIdx.x * 16;
    const int tid = threadIdx.x;
    const int cidx = tid & 15;  // class within tile
    const int qg = tid >> 4;    // query group (8 queries each)

    float acc[8][8];  // [qi][k]
#pragma unroll
    for (int i = 0; i < 8; i++)
#pragma unroll
        for (int k = 0; k < 8; k++) acc[i][k] = 0.0f;

    for (int d0 = 0; d0 < 512; d0 += 32) {
        // A tile: 128 q x 32 d  (1024 float4, 4 per thread), store as [d][q]
#pragma unroll
        for (int it = 0; it < 4; it++) {
            int i4 = tid + it * 256;
            int q = i4 >> 3;
            int dd = (i4 & 7) * 4;
            float4 v = *(const float4*)(query + (size_t)(q0 + q) * 512 + d0 + dd);
            As[dd + 0][q] = v.x;
            As[dd + 1][q] = v.y;
            As[dd + 2][q] = v.z;
            As[dd + 3][q] = v.w;
        }
        // B tile: 16 c x 32 d x 8 k. Per class the chunk T[(c0+c)*4096 + d0*8 .. +256)
        // is contiguous; store as Bs[d][c*8+k].
#pragma unroll
        for (int it = 0; it < 4; it++) {
            int i4 = tid + it * 256;
            int c = i4 >> 6;            // 0..15
            int rem = (i4 & 63) * 4;    // float position within 256-chunk
            int dl = rem >> 3;          // 0..31
            int kk = rem & 7;           // 0 or 4
            float4 v = *(const float4*)(T + (size_t)(c0 + c) * 4096 + d0 * 8 + rem);
            *(float4*)&Bs[dl][c * 8 + kk] = v;
        }
        __syncthreads();

#pragma unroll 8
        for (int dd = 0; dd < 32; dd++) {
            float4 b0 = *(const float4*)&Bs[dd][cidx * 8];
            float4 b1 = *(const float4*)&Bs[dd][cidx * 8 + 4];
            float4 a0 = *(const float4*)&As[dd][qg * 8];
            float4 a1 = *(const float4*)&As[dd][qg * 8 + 4];
            float a[8] = {a0.x, a0.y, a0.z, a0.w, a1.x, a1.y, a1.z, a1.w};
#pragma unroll
            for (int i = 0; i < 8; i++) {
                acc[i][0] = fmaf(a[i], b0.x, acc[i][0]);
                acc[i][1] = fmaf(a[i], b0.y, acc[i][1]);
                acc[i][2] = fmaf(a[i], b0.z, acc[i][2]);
                acc[i][3] = fmaf(a[i], b0.w, acc[i][3]);
                acc[i][4] = fmaf(a[i], b1.x, acc[i][4]);
                acc[i][5] = fmaf(a[i], b1.y, acc[i][5]);
                acc[i][6] = fmaf(a[i], b1.z, acc[i][6]);
                acc[i][7] = fmaf(a[i], b1.w, acc[i][7]);
            }
        }
        __syncthreads();
    }

    // Epilogue: relu -> weighted sum over k -> store
    float w[8];
#pragma unroll
    for (int k = 0; k < 8; k++) w[k] = score_w[k];
    float sb = score_b[0];

#pragma unroll
    for (int i = 0; i < 8; i++) {
        float s = sb;
#pragma unroll
        for (int k = 0; k < 8; k++) s = fmaf(fmaxf(acc[i][k], 0.0f), w[k], s);
        other[(size_t)(q0 + qg * 8 + i) * 4096 + c0 + cidx] = s;
    }
}

// ---------------------------------------------------------------------------
// Row softmax, in place, one block (256 threads) per row of 4096.
// ---------------------------------------------------------------------------
__global__ void softmax_rows(float* __restrict__ o)
{
    const int row = blockIdx.x;
    float* p = o + (size_t)row * 4096;
    const int tid = threadIdx.x;

    float v[16];
    float mx = -1e30f;
#pragma unroll
    for (int i = 0; i < 16; i++) {
        v[i] = p[tid + (i << 8)];
        mx = fmaxf(mx, v[i]);
    }

    __shared__ float sm[8];
#pragma unroll
    for (int o2 = 16; o2 > 0; o2 >>= 1)
        mx = fmaxf(mx, __shfl_xor_sync(0xffffffffu, mx, o2));
    if ((tid & 31) == 0) sm[tid >> 5] = mx;
    __syncthreads();
    mx = sm[0];
#pragma unroll
    for (int i = 1; i < 8; i++) mx = fmaxf(mx, sm[i]);
    __syncthreads();

    float s = 0.0f;
#pragma unroll
    for (int i = 0; i < 16; i++) {
        v[i] = expf(v[i] - mx);
        s += v[i];
    }
#pragma unroll
    for (int o2 = 16; o2 > 0; o2 >>= 1)
        s += __shfl_xor_sync(0xffffffffu, s, o2);
    if ((tid & 31) == 0) sm[tid >> 5] = s;
    __syncthreads();
    s = 0.0f;
#pragma unroll
    for (int i = 0; i < 8; i++) s += sm[i];

    float inv = 1.0f / s;
#pragma unroll
    for (int i = 0; i < 16; i++) p[tid + (i << 8)] = v[i] * inv;
}

// ---------------------------------------------------------------------------
// Transpose hash_w [64,512] -> g_hwT [512,64]
// ---------------------------------------------------------------------------
__global__ void transpose_hw(const float* __restrict__ hw)
{
    int idx = blockIdx.x * blockDim.x + threadIdx.x;  // 0..32767
    int l = idx >> 9;
    int d = idx & 511;
    g_hwT[d * 64 + l] = hw[idx];
}

// ---------------------------------------------------------------------------
extern "C" void kernel_launch(void* const* d_in, const int* in_sizes, int n_in,
                              void* d_out, int out_size)
{
    const float* class_v = (const float*)d_in[0];  // [4096,512]
    const float* query_v = (const float*)d_in[1];  // [4096,512]
    const float* Mmat    = (const float*)d_in[2];  // [512,512,8] == [i][(j,k)]
    const float* score_w = (const float*)d_in[3];  // [8]
    const float* score_b = (const float*)d_in[4];  // [1]
    const float* hash_w  = (const float*)d_in[5];  // [64,512]
    const float* hash_b  = (const float*)d_in[6];  // [64]
    float* out = (float*)d_out;                    // [4096,64]

    float *T, *other, *qf, *hwT;
    cudaGetSymbolAddress((void**)&T, g_T);
    cudaGetSymbolAddress((void**)&other, g_other);
    cudaGetSymbolAddress((void**)&qf, g_qf);
    cudaGetSymbolAddress((void**)&hwT, g_hwT);

    // Stage 0: transpose hash_w (tiny)
    transpose_hw<<<128, 256>>>(hash_w);

    // Stage 1: T = class @ M_reshaped   [4096 x 4096, K=512]
    gemm_f32<128, 128, 16, 8, 8, 0><<<dim3(32, 32), 256>>>(
        class_v, Mmat, nullptr, T, 4096, 4096, 512);

    // Stage 2: fused bilinear + relu + score -> other [4096 x 4096]
    bilinear_score_kernel<<<dim3(256, 32), 256>>>(query_v, T, score_w, score_b, other);

    // Stage 3: softmax over class dim (in place)
    softmax_rows<<<4096, 256>>>(other);

    // Stage 4: qf = scores @ class + query   [4096 x 512, K=4096]
    gemm_f32<128, 128, 16, 8, 8, 1><<<dim3(4, 32), 256>>>(
        other, class_v, query_v, qf, 4096, 512, 4096);

    // Stage 5: out = tanh(qf @ hwT + hash_b)   [4096 x 64, K=512]
    gemm_f32<64, 64, 16, 4, 4, 2><<<dim3(1, 64), 256>>>(
        qf, hwT, hash_b, out, 4096, 64, 512);
}

// round 4
// speedup vs baseline: 1.9176x; 1.9147x over previous
#include <cuda_runtime.h>
#include <math.h>
#include <stdint.h>

// ---------------------------------------------------------------------------
// Dims: D=512, K=8, L=64, Q=4096, C=4096
// Pipeline:
//   Tk[k][c][d] = sum_i class[c,i]*M[i,d,k]      (SIMT GEMM, tf32-rounded scatter)
//   other[q,c]  = b + sum_k w_k*relu(sum_d qtf[q,d]*Tk[k][c][d])   (mma.sync tf32)
//   scores      = softmax_rows(other)
//   qf          = scores @ class + query          (SIMT GEMM)
//   out         = tanh(qf @ hash_w^T + hash_b)    (SIMT GEMM)
// NOTE: harness ptxas target is sm_103 (no 'a') -> tcgen05/TMEM unavailable.
// mma.sync (HMMA), cp.async, cvt.rna.tf32 are sm_80+ and legal.
// ---------------------------------------------------------------------------

__device__ float g_T[(size_t)8 * 4096 * 512];   // 64 MB: Tk[k][c][d] (tf32-rounded)
__device__ float g_other[(size_t)4096 * 4096];  // 64 MB
__device__ float g_qf[(size_t)4096 * 512];      // 8 MB
__device__ float g_qtf[(size_t)4096 * 512];     // 8 MB: tf32-rounded query
__device__ float g_hwT[512 * 64];

// ------------------------------ helpers -----------------------------------
__device__ __forceinline__ uint32_t smem_u32(const void* p) {
    uint32_t a;
    asm("{ .reg .u64 t; cvta.to.shared.u64 t, %1; cvt.u32.u64 %0, t; }" : "=r"(a) : "l"(p));
    return a;
}
__device__ __forceinline__ float tf32r(float x) {
    unsigned u;
    asm("cvt.rna.tf32.f32 %0, %1;" : "=r"(u) : "f"(x));
    return __uint_as_float(u);
}
__device__ __forceinline__ void mma_tf32(float* c, const float* a, const float* b) {
    asm volatile(
        "mma.sync.aligned.m16n8k8.row.col.f32.tf32.tf32.f32 "
        "{%0,%1,%2,%3}, {%4,%5,%6,%7}, {%8,%9}, {%0,%1,%2,%3};"
        : "+f"(c[0]), "+f"(c[1]), "+f"(c[2]), "+f"(c[3])
        : "r"(__float_as_uint(a[0])), "r"(__float_as_uint(a[1])),
          "r"(__float_as_uint(a[2])), "r"(__float_as_uint(a[3])),
          "r"(__float_as_uint(b[0])), "r"(__float_as_uint(b[1])));
}

// ---------------------------------------------------------------------------
// Generic tiled fp32 GEMM (SIMT), epilogues:
//   0: plain   1: +X[r,c]   2: tanh(+X[c])   3: scatter to Tk[k][c][d] tf32-rounded
// ---------------------------------------------------------------------------
template <int BM, int BN, int BK, int TM, int TN, int EPI>
__global__ void __launch_bounds__((BM / TM) * (BN / TN), 2)
gemm_f32(const float* __restrict__ A, const float* __restrict__ B,
         const float* __restrict__ X, float* __restrict__ out,
         int M, int N, int K)
{
    constexpr int THREADS = (BM / TM) * (BN / TN);
    __shared__ float As[BK][BM + 4];
    __shared__ float Bs[BK][BN + 4];

    const int bm = blockIdx.y * BM;
    const int bn = blockIdx.x * BN;
    const int tid = threadIdx.x;
    const int tcol = tid % (BN / TN);
    const int trow = tid / (BN / TN);

    float acc[TM][TN];
#pragma unroll
    for (int i = 0; i < TM; i++)
#pragma unroll
        for (int j = 0; j < TN; j++) acc[i][j] = 0.0f;

    for (int k0 = 0; k0 < K; k0 += BK) {
#pragma unroll
        for (int it = 0; it < (BM * BK / 4) / THREADS; it++) {
            int i = tid + it * THREADS;
            int r = i / (BK / 4);
            int c4 = (i % (BK / 4)) * 4;
            float4 v = *(const float4*)(A + (size_t)(bm + r) * K + k0 + c4);
            As[c4 + 0][r] = v.x; As[c4 + 1][r] = v.y;
            As[c4 + 2][r] = v.z; As[c4 + 3][r] = v.w;
        }
#pragma unroll
        for (int it = 0; it < (BK * BN / 4) / THREADS; it++) {
            int i = tid + it * THREADS;
            int r = i / (BN / 4);
            int c4 = (i % (BN / 4)) * 4;
            *(float4*)&Bs[r][c4] = *(const float4*)(B + (size_t)(k0 + r) * N + bn + c4);
        }
        __syncthreads();

#pragma unroll
        for (int kk = 0; kk < BK; kk++) {
            float af[TM], bf[TN];
#pragma unroll
            for (int i = 0; i < TM; i += 4) {
                float4 v = *(const float4*)&As[kk][trow * TM + i];
                af[i] = v.x; af[i + 1] = v.y; af[i + 2] = v.z; af[i + 3] = v.w;
            }
#pragma unroll
            for (int j = 0; j < TN; j += 4) {
                float4 v = *(const float4*)&Bs[kk][tcol * TN + j];
                bf[j] = v.x; bf[j + 1] = v.y; bf[j + 2] = v.z; bf[j + 3] = v.w;
            }
#pragma unroll
            for (int i = 0; i < TM; i++)
#pragma unroll
                for (int j = 0; j < TN; j++)
                    acc[i][j] = fmaf(af[i], bf[j], acc[i][j]);
        }
        __syncthreads();
    }

#pragma unroll
    for (int i = 0; i < TM; i++) {
        int r = bm + trow * TM + i;
#pragma unroll
        for (int j = 0; j < TN; j++) {
            int c = bn + tcol * TN + j;
            float v = acc[i][j];
            if (EPI == 3) {
                // column c = j_dim*8 + k  ->  Tk[k][r][j_dim], tf32-rounded
                size_t idx = ((size_t)(c & 7) << 21) + (size_t)r * 512 + (size_t)(c >> 3);
                out[idx] = tf32r(v);
            } else {
                if (EPI == 1) v += X[(size_t)r * N + c];
                else if (EPI == 2) v = tanhf(v + X[c]);
                out[(size_t)r * N + c] = v;
            }
        }
    }
}

// ---------------------------------------------------------------------------
// Stage 2: mma.sync tf32 fused bilinear + relu + score.
//   other[q,c] = b + sum_k w_k * relu( sum_d qtf[q,d] * Tk[k][c][d] )
// CTA 128q x 128c, 8 warps (2m x 4n), warp tile 64x32.
// Double-buffered cp.async, d-chunks of 32 (layout [row][36] floats, padded).
// ---------------------------------------------------------------------------
#define S2_ROWPAD 36
#define S2_TILE (128 * S2_ROWPAD)             // floats per (buf) per operand
#define S2_SMEM (4 * S2_TILE * 4)             // 2 bufs x (A+B) = 73728 B

__device__ __forceinline__ void s2_load(float* As, float* Bs,
                                        const float* __restrict__ qtf,
                                        const float* __restrict__ Tk,
                                        int q0, int c0, int tid, int k, int t, int buf)
{
    const int row = tid >> 3;          // 0..31 (+32*i)
    const int f4 = (tid & 7) * 4;      // 0,4,...,28
    const float* ga = qtf + (size_t)(q0 + row) * 512 + t * 32 + f4;
    const float* gb = Tk + ((size_t)k << 21) + (size_t)(c0 + row) * 512 + t * 32 + f4;
    uint32_t da = smem_u32(As + buf * S2_TILE + row * S2_ROWPAD + f4);
    uint32_t db = smem_u32(Bs + buf * S2_TILE + row * S2_ROWPAD + f4);
#pragma unroll
    for (int i = 0; i < 4; i++) {
        asm volatile("cp.async.cg.shared.global [%0], [%1], 16;"
                     :: "r"(da + i * 32 * S2_ROWPAD * 4), "l"(ga + (size_t)i * 32 * 512));
        asm volatile("cp.async.cg.shared.global [%0], [%1], 16;"
                     :: "r"(db + i * 32 * S2_ROWPAD * 4), "l"(gb + (size_t)i * 32 * 512));
    }
    asm volatile("cp.async.commit_group;" ::: "memory");
}

__global__ void __launch_bounds__(256, 1)
stage2_mma(const float* __restrict__ qtf, const float* __restrict__ Tk,
           const float* __restrict__ score_w, const float* __restrict__ score_b,
           float* __restrict__ other)
{
    extern __shared__ float smf[];
    float* As = smf;                 // [2][128][36]  (q rows)
    float* Bs = smf + 2 * S2_TILE;   // [2][128][36]  (c rows)

    const int tid = threadIdx.x;
    const int lane = tid & 31;
    const int wid = tid >> 5;
    const int wm = wid >> 2;         // 0..1 -> 64 q rows each
    const int wn = wid & 3;          // 0..3 -> 32 c cols each
    const int q0 = blockIdx.y * 128;
    const int c0 = blockIdx.x * 128;

    const int lq = lane >> 2;        // 0..7
    const int ld = lane & 3;         // 0..3

    float sacc[4][4][4];
#pragma unroll
    for (int mi = 0; mi < 4; mi++)
#pragma unroll
        for (int ni = 0; ni < 4; ni++)
#pragma unroll
            for (int r = 0; r < 4; r++) sacc[mi][ni][r] = 0.0f;

    for (int k = 0; k < 8; k++) {
        float macc[4][4][4];
#pragma unroll
        for (int mi = 0; mi < 4; mi++)
#pragma unroll
            for (int ni = 0; ni < 4; ni++)
#pragma unroll
                for (int r = 0; r < 4; r++) macc[mi][ni][r] = 0.0f;

        s2_load(As, Bs, qtf, Tk, q0, c0, tid, k, 0, 0);

        for (int t = 0; t < 16; t++) {
            const int buf = t & 1;
            if (t < 15) {
                s2_load(As, Bs, qtf, Tk, q0, c0, tid, k, t + 1, buf ^ 1);
                asm volatile("cp.async.wait_group 1;" ::: "memory");
            } else {
                asm volatile("cp.async.wait_group 0;" ::: "memory");
            }
            __syncthreads();

            const float* pa = As + buf * S2_TILE;
            const float* pb = Bs + buf * S2_TILE;
#pragma unroll
            for (int d8 = 0; d8 < 4; d8++) {
                float a[4][4], b[4][2];
#pragma unroll
                for (int mi = 0; mi < 4; mi++) {
                    const float* p = pa + (wm * 64 + mi * 16 + lq) * S2_ROWPAD + d8 * 8 + ld;
                    a[mi][0] = p[0];
                    a[mi][1] = p[8 * S2_ROWPAD];
                    a[mi][2] = p[4];
                    a[mi][3] = p[8 * S2_ROWPAD + 4];
                }
#pragma unroll
                for (int ni = 0; ni < 4; ni++) {
                    const float* p = pb + (wn * 32 + ni * 8 + lq) * S2_ROWPAD + d8 * 8 + ld;
                    b[ni][0] = p[0];
                    b[ni][1] = p[4];
                }
#pragma unroll
                for (int mi = 0; mi < 4; mi++)
#pragma unroll
                    for (int ni = 0; ni < 4; ni++)
                        mma_tf32(macc[mi][ni], a[mi], b[ni]);
            }
            __syncthreads();
        }

        const float w = __ldg(score_w + k);
#pragma unroll
        for (int mi = 0; mi < 4; mi++)
#pragma unroll
            for (int ni = 0; ni < 4; ni++)
#pragma unroll
                for (int r = 0; r < 4; r++)
                    sacc[mi][ni][r] = fmaf(fmaxf(macc[mi][ni][r], 0.0f), w, sacc[mi][ni][r]);
    }

    const float sb = __ldg(score_b);
#pragma unroll
    for (int mi = 0; mi < 4; mi++) {
        const int q = q0 + wm * 64 + mi * 16 + lq;
#pragma unroll
        for (int ni = 0; ni < 4; ni++) {
            const int c = c0 + wn * 32 + ni * 8 + 2 * ld;
            float2 v0 = make_float2(sb + sacc[mi][ni][0], sb + sacc[mi][ni][1]);
            float2 v1 = make_float2(sb + sacc[mi][ni][2], sb + sacc[mi][ni][3]);
            *(float2*)(other + (size_t)q * 4096 + c) = v0;
            *(float2*)(other + (size_t)(q + 8) * 4096 + c) = v1;
        }
    }
}

// ---------------------------------------------------------------------------
__global__ void softmax_rows(float* __restrict__ o)
{
    const int row = blockIdx.x;
    float* p = o + (size_t)row * 4096;
    const int tid = threadIdx.x;

    float v[16];
    float mx = -1e30f;
#pragma unroll
    for (int i = 0; i < 16; i++) {
        v[i] = p[tid + (i << 8)];
        mx = fmaxf(mx, v[i]);
    }
    __shared__ float sm[8];
#pragma unroll
    for (int o2 = 16; o2 > 0; o2 >>= 1)
        mx = fmaxf(mx, __shfl_xor_sync(0xffffffffu, mx, o2));
    if ((tid & 31) == 0) sm[tid >> 5] = mx;
    __syncthreads();
    mx = sm[0];
#pragma unroll
    for (int i = 1; i < 8; i++) mx = fmaxf(mx, sm[i]);
    __syncthreads();

    float s = 0.0f;
#pragma unroll
    for (int i = 0; i < 16; i++) { v[i] = expf(v[i] - mx); s += v[i]; }
#pragma unroll
    for (int o2 = 16; o2 > 0; o2 >>= 1)
        s += __shfl_xor_sync(0xffffffffu, s, o2);
    if ((tid & 31) == 0) sm[tid >> 5] = s;
    __syncthreads();
    s = 0.0f;
#pragma unroll
    for (int i = 0; i < 8; i++) s += sm[i];
    float inv = 1.0f / s;
#pragma unroll
    for (int i = 0; i < 16; i++) p[tid + (i << 8)] = v[i] * inv;
}

__global__ void transpose_hw(const float* __restrict__ hw)
{
    int idx = blockIdx.x * blockDim.x + threadIdx.x;
    int l = idx >> 9;
    int d = idx & 511;
    g_hwT[d * 64 + l] = hw[idx];
}

__global__ void round_query(const float* __restrict__ q)
{
    int idx = blockIdx.x * blockDim.x + threadIdx.x;  // 0..2097151
    g_qtf[idx] = tf32r(q[idx]);
}

// ---------------------------------------------------------------------------
extern "C" void kernel_launch(void* const* d_in, const int* in_sizes, int n_in,
                              void* d_out, int out_size)
{
    const float* class_v = (const float*)d_in[0];
    const float* query_v = (const float*)d_in[1];
    const float* Mmat    = (const float*)d_in[2];
    const float* score_w = (const float*)d_in[3];
    const float* score_b = (const float*)d_in[4];
    const float* hash_w  = (const float*)d_in[5];
    const float* hash_b  = (const float*)d_in[6];
    float* out = (float*)d_out;

    float *T, *other, *qf, *hwT, *qtf;
    cudaGetSymbolAddress((void**)&T, g_T);
    cudaGetSymbolAddress((void**)&other, g_other);
    cudaGetSymbolAddress((void**)&qf, g_qf);
    cudaGetSymbolAddress((void**)&hwT, g_hwT);
    cudaGetSymbolAddress((void**)&qtf, g_qtf);

    cudaFuncSetAttribute(stage2_mma, cudaFuncAttributeMaxDynamicSharedMemorySize, S2_SMEM);

    transpose_hw<<<128, 256>>>(hash_w);
    round_query<<<8192, 256>>>(query_v);

    // Stage 1: Tk[k][c][d] = class @ M (scatter + tf32-round epilogue)
    gemm_f32<128, 128, 16, 8, 8, 3><<<dim3(32, 32), 256>>>(
        class_v, Mmat, nullptr, T, 4096, 4096, 512);

    // Stage 2: mma.sync tf32 fused bilinear+relu+score
    stage2_mma<<<dim3(32, 32), 256, S2_SMEM>>>(qtf, T, score_w, score_b, other);

    // Stage 3: softmax
    softmax_rows<<<4096, 256>>>(other);

    // Stage 4: qf = scores @ class + query
    gemm_f32<128, 128, 16, 8, 8, 1><<<dim3(4, 32), 256>>>(
        other, class_v, query_v, qf, 4096, 512, 4096);

    // Stage 5: out = tanh(qf @ hwT + hash_b)
    gemm_f32<64, 64, 16, 4, 4, 2><<<dim3(1, 64), 256>>>(
        qf, hwT, hash_b, out, 4096, 64, 512);
}

// round 5
// speedup vs baseline: 2.1358x; 1.1138x over previous
#include <cuda_runtime.h>
#include <math.h>
#include <stdint.h>

// ---------------------------------------------------------------------------
// Dims: D=512, K=8, L=64, Q=4096, C=4096
//   Tk[k][c][d] = sum_i class[c,i]*M[i,d,k]       (3xTF32 mma GEMM, scatter)
//   other[q,c]  = b + sum_k w_k*relu(sum_d qtf[q,d]*Tk[k][c][d])  (tf32 mma)
//   scores      = softmax_rows(other)
//   qf          = scores @ class + query           (3xTF32 mma, split-K=4)
//   out         = tanh(qf @ hash_w^T + hash_b)     (SIMT GEMM)
// Target sm_103 (no 'a'): mma.sync/cp.async only, no tcgen05.
// ---------------------------------------------------------------------------

__device__ float g_T[(size_t)8 * 4096 * 512];    // 64 MB: Tk[k][c][d]
__device__ float g_other[(size_t)4096 * 4096];   // 64 MB
__device__ float g_qf[(size_t)4096 * 512];       // 8 MB
__device__ float g_qtf[(size_t)4096 * 512];      // 8 MB tf32-rounded query
__device__ float g_hwT[512 * 64];
__device__ float g_MT_hi[(size_t)4096 * 512];    // M^T  [jk][i] hi
__device__ float g_MT_lo[(size_t)4096 * 512];    //               lo
__device__ float g_clT_hi[(size_t)512 * 4096];   // class^T [d][c] hi
__device__ float g_clT_lo[(size_t)512 * 4096];   //               lo
__device__ float g_qfp[(size_t)4 * 4096 * 512];  // 32 MB split-K partials

// ------------------------------ helpers -----------------------------------
__device__ __forceinline__ uint32_t smem_u32(const void* p) {
    uint32_t a;
    asm("{ .reg .u64 t; cvta.to.shared.u64 t, %1; cvt.u32.u64 %0, t; }" : "=r"(a) : "l"(p));
    return a;
}
__device__ __forceinline__ float tf32r(float x) {
    unsigned u;
    asm("cvt.rna.tf32.f32 %0, %1;" : "=r"(u) : "f"(x));
    return __uint_as_float(u);
}
__device__ __forceinline__ void mma_tf32(float* c, const float* a, const float* b) {
    asm volatile(
        "mma.sync.aligned.m16n8k8.row.col.f32.tf32.tf32.f32 "
        "{%0,%1,%2,%3}, {%4,%5,%6,%7}, {%8,%9}, {%0,%1,%2,%3};"
        : "+f"(c[0]), "+f"(c[1]), "+f"(c[2]), "+f"(c[3])
        : "r"(__float_as_uint(a[0])), "r"(__float_as_uint(a[1])),
          "r"(__float_as_uint(a[2])), "r"(__float_as_uint(a[3])),
          "r"(__float_as_uint(b[0])), "r"(__float_as_uint(b[1])));
}

// ---------------------------------------------------------------------------
// Generic tiled fp32 SIMT GEMM (kept for stage 5). EPI 2: tanh(acc + X[c]).
// ---------------------------------------------------------------------------
template <int BM, int BN, int BK, int TM, int TN, int EPI>
__global__ void __launch_bounds__((BM / TM) * (BN / TN), 2)
gemm_f32(const float* __restrict__ A, const float* __restrict__ B,
         const float* __restrict__ X, float* __restrict__ out,
         int M, int N, int K)
{
    constexpr int THREADS = (BM / TM) * (BN / TN);
    __shared__ float As[BK][BM + 4];
    __shared__ float Bs[BK][BN + 4];

    const int bm = blockIdx.y * BM;
    const int bn = blockIdx.x * BN;
    const int tid = threadIdx.x;
    const int tcol = tid % (BN / TN);
    const int trow = tid / (BN / TN);

    float acc[TM][TN];
#pragma unroll
    for (int i = 0; i < TM; i++)
#pragma unroll
        for (int j = 0; j < TN; j++) acc[i][j] = 0.0f;

    for (int k0 = 0; k0 < K; k0 += BK) {
#pragma unroll
        for (int it = 0; it < (BM * BK / 4) / THREADS; it++) {
            int i = tid + it * THREADS;
            int r = i / (BK / 4);
            int c4 = (i % (BK / 4)) * 4;
            float4 v = *(const float4*)(A + (size_t)(bm + r) * K + k0 + c4);
            As[c4 + 0][r] = v.x; As[c4 + 1][r] = v.y;
            As[c4 + 2][r] = v.z; As[c4 + 3][r] = v.w;
        }
#pragma unroll
        for (int it = 0; it < (BK * BN / 4) / THREADS; it++) {
            int i = tid + it * THREADS;
            int r = i / (BN / 4);
            int c4 = (i % (BN / 4)) * 4;
            *(float4*)&Bs[r][c4] = *(const float4*)(B + (size_t)(k0 + r) * N + bn + c4);
        }
        __syncthreads();

#pragma unroll
        for (int kk = 0; kk < BK; kk++) {
            float af[TM], bf[TN];
#pragma unroll
            for (int i = 0; i < TM; i += 4) {
                float4 v = *(const float4*)&As[kk][trow * TM + i];
                af[i] = v.x; af[i + 1] = v.y; af[i + 2] = v.z; af[i + 3] = v.w;
            }
#pragma unroll
            for (int j = 0; j < TN; j += 4) {
                float4 v = *(const float4*)&Bs[kk][tcol * TN + j];
                bf[j] = v.x; bf[j + 1] = v.y; bf[j + 2] = v.z; bf[j + 3] = v.w;
            }
#pragma unroll
            for (int i = 0; i < TM; i++)
#pragma unroll
                for (int j = 0; j < TN; j++)
                    acc[i][j] = fmaf(af[i], bf[j], acc[i][j]);
        }
        __syncthreads();
    }

#pragma unroll
    for (int i = 0; i < TM; i++) {
        int r = bm + trow * TM + i;
#pragma unroll
        for (int j = 0; j < TN; j++) {
            int c = bn + tcol * TN + j;
            float v = acc[i][j];
            if (EPI == 2) v = tanhf(v + X[c]);
            out[(size_t)r * N + c] = v;
        }
    }
}

// ---------------------------------------------------------------------------
// 3xTF32 mma GEMM: out = A[M,Kr] @ Bt[N,Kr]^T, near-fp32 accuracy.
// A fp32 (hi/lo split in registers); Bt pre-split into Bhi/Blo.
// CTA 128m x 128n, 8 warps (2x4), warp tile 64x32, chunk=32, double buffer.
// kseg: reduction length per z-slice; kstart = z*kseg.
//   EPI 0: scatter tf32r(v) to Tk layout ((c&7)<<21) + r*512 + (c>>3)
//   EPI 1: store partial to out + z*4096*512 at [r*512+c]
// ---------------------------------------------------------------------------
#define G3_PAD 36
#define G3_TILE (128 * G3_PAD)
#define G3_SMEM (6 * G3_TILE * 4)   // 110592 B

template <int EPI>
__device__ __forceinline__ void g3_load(float* As, float* Bh, float* Bl,
                                        const float* __restrict__ A,
                                        const float* __restrict__ Bhi,
                                        const float* __restrict__ Blo,
                                        int m0, int n0, int lda, int ldb,
                                        int kofs, int tid, int buf)
{
    const int row = tid >> 3;
    const int f4 = (tid & 7) * 4;
    uint32_t da = smem_u32(As + buf * G3_TILE + row * G3_PAD + f4);
    uint32_t dh = smem_u32(Bh + buf * G3_TILE + row * G3_PAD + f4);
    uint32_t dl = smem_u32(Bl + buf * G3_TILE + row * G3_PAD + f4);
    const float* ga = A + (size_t)(m0 + row) * lda + kofs + f4;
    const float* gh = Bhi + (size_t)(n0 + row) * ldb + kofs + f4;
    const float* gl = Blo + (size_t)(n0 + row) * ldb + kofs + f4;
#pragma unroll
    for (int i = 0; i < 4; i++) {
        asm volatile("cp.async.cg.shared.global [%0], [%1], 16;"
                     :: "r"(da + i * 32 * G3_PAD * 4), "l"(ga + (size_t)i * 32 * lda));
        asm volatile("cp.async.cg.shared.global [%0], [%1], 16;"
                     :: "r"(dh + i * 32 * G3_PAD * 4), "l"(gh + (size_t)i * 32 * ldb));
        asm volatile("cp.async.cg.shared.global [%0], [%1], 16;"
                     :: "r"(dl + i * 32 * G3_PAD * 4), "l"(gl + (size_t)i * 32 * ldb));
    }
    asm volatile("cp.async.commit_group;" ::: "memory");
}

template <int EPI>
__global__ void __launch_bounds__(256, 1)
gemm3x(const float* __restrict__ A,
       const float* __restrict__ Bhi, const float* __restrict__ Blo,
       float* __restrict__ out, int lda, int ldb, int kseg)
{
    extern __shared__ float smf[];
    float* As = smf;
    float* Bh = smf + 2 * G3_TILE;
    float* Bl = smf + 4 * G3_TILE;

    const int tid = threadIdx.x;
    const int lane = tid & 31;
    const int wid = tid >> 5;
    const int wm = wid >> 2;
    const int wn = wid & 3;
    const int m0 = blockIdx.y * 128;
    const int n0 = blockIdx.x * 128;
    const int kstart = blockIdx.z * kseg;
    const int nchunks = kseg / 32;

    const int lq = lane >> 2;
    const int ld = lane & 3;

    float macc[4][4][4];
#pragma unroll
    for (int mi = 0; mi < 4; mi++)
#pragma unroll
        for (int ni = 0; ni < 4; ni++)
#pragma unroll
            for (int r = 0; r < 4; r++) macc[mi][ni][r] = 0.0f;

    g3_load<EPI>(As, Bh, Bl, A, Bhi, Blo, m0, n0, lda, ldb, kstart, tid, 0);

    for (int t = 0; t < nchunks; t++) {
        const int buf = t & 1;
        if (t < nchunks - 1) {
            g3_load<EPI>(As, Bh, Bl, A, Bhi, Blo, m0, n0, lda, ldb,
                         kstart + (t + 1) * 32, tid, buf ^ 1);
            asm volatile("cp.async.wait_group 1;" ::: "memory");
        } else {
            asm volatile("cp.async.wait_group 0;" ::: "memory");
        }
        __syncthreads();

        const float* pa = As + buf * G3_TILE;
        const float* ph = Bh + buf * G3_TILE;
        const float* pl = Bl + buf * G3_TILE;
#pragma unroll
        for (int d8 = 0; d8 < 4; d8++) {
            float ahi[4][4], alo[4][4];
#pragma unroll
            for (int mi = 0; mi < 4; mi++) {
                const float* p = pa + (wm * 64 + mi * 16 + lq) * G3_PAD + d8 * 8 + ld;
                float a0 = p[0], a1 = p[8 * G3_PAD], a2 = p[4], a3 = p[8 * G3_PAD + 4];
                ahi[mi][0] = tf32r(a0); alo[mi][0] = tf32r(a0 - ahi[mi][0]);
                ahi[mi][1] = tf32r(a1); alo[mi][1] = tf32r(a1 - ahi[mi][1]);
                ahi[mi][2] = tf32r(a2); alo[mi][2] = tf32r(a2 - ahi[mi][2]);
                ahi[mi][3] = tf32r(a3); alo[mi][3] = tf32r(a3 - ahi[mi][3]);
            }
            float bh[4][2], bl[4][2];
#pragma unroll
            for (int ni = 0; ni < 4; ni++) {
                const float* p = ph + (wn * 32 + ni * 8 + lq) * G3_PAD + d8 * 8 + ld;
                bh[ni][0] = p[0]; bh[ni][1] = p[4];
                const float* p2 = pl + (wn * 32 + ni * 8 + lq) * G3_PAD + d8 * 8 + ld;
                bl[ni][0] = p2[0]; bl[ni][1] = p2[4];
            }
#pragma unroll
            for (int mi = 0; mi < 4; mi++)
#pragma unroll
                for (int ni = 0; ni < 4; ni++) {
                    mma_tf32(macc[mi][ni], ahi[mi], bh[ni]);
                    mma_tf32(macc[mi][ni], alo[mi], bh[ni]);
                    mma_tf32(macc[mi][ni], ahi[mi], bl[ni]);
                }
        }
        __syncthreads();
    }

    // epilogue
    if (EPI == 0) {
#pragma unroll
        for (int mi = 0; mi < 4; mi++) {
            const int r = m0 + wm * 64 + mi * 16 + lq;
#pragma unroll
            for (int ni = 0; ni < 4; ni++) {
                const int c = n0 + wn * 32 + ni * 8 + 2 * ld;
#pragma unroll
                for (int rr = 0; rr < 4; rr++) {
                    int row = r + (rr >> 1) * 8;
                    int col = c + (rr & 1);
                    size_t idx = ((size_t)(col & 7) << 21) + (size_t)row * 512 + (size_t)(col >> 3);
                    out[idx] = tf32r(macc[mi][ni][rr]);
                }
            }
        }
    } else {
        float* ob = out + (size_t)blockIdx.z * 4096 * 512;
#pragma unroll
        for (int mi = 0; mi < 4; mi++) {
            const int r = m0 + wm * 64 + mi * 16 + lq;
#pragma unroll
            for (int ni = 0; ni < 4; ni++) {
                const int c = n0 + wn * 32 + ni * 8 + 2 * ld;
                *(float2*)(ob + (size_t)r * 512 + c) =
                    make_float2(macc[mi][ni][0], macc[mi][ni][1]);
                *(float2*)(ob + (size_t)(r + 8) * 512 + c) =
                    make_float2(macc[mi][ni][2], macc[mi][ni][3]);
            }
        }
    }
}

// ---------------------------------------------------------------------------
// Stage 2: mma.sync tf32 fused bilinear + relu + score. (unchanged from R4)
// ---------------------------------------------------------------------------
#define S2_ROWPAD 36
#define S2_TILE (128 * S2_ROWPAD)
#define S2_SMEM (4 * S2_TILE * 4)

__device__ __forceinline__ void s2_load(float* As, float* Bs,
                                        const float* __restrict__ qtf,
                                        const float* __restrict__ Tk,
                                        int q0, int c0, int tid, int k, int t, int buf)
{
    const int row = tid >> 3;
    const int f4 = (tid & 7) * 4;
    const float* ga = qtf + (size_t)(q0 + row) * 512 + t * 32 + f4;
    const float* gb = Tk + ((size_t)k << 21) + (size_t)(c0 + row) * 512 + t * 32 + f4;
    uint32_t da = smem_u32(As + buf * S2_TILE + row * S2_ROWPAD + f4);
    uint32_t db = smem_u32(Bs + buf * S2_TILE + row * S2_ROWPAD + f4);
#pragma unroll
    for (int i = 0; i < 4; i++) {
        asm volatile("cp.async.cg.shared.global [%0], [%1], 16;"
                     :: "r"(da + i * 32 * S2_ROWPAD * 4), "l"(ga + (size_t)i * 32 * 512));
        asm volatile("cp.async.cg.shared.global [%0], [%1], 16;"
                     :: "r"(db + i * 32 * S2_ROWPAD * 4), "l"(gb + (size_t)i * 32 * 512));
    }
    asm volatile("cp.async.commit_group;" ::: "memory");
}

__global__ void __launch_bounds__(256, 1)
stage2_mma(const float* __restrict__ qtf, const float* __restrict__ Tk,
           const float* __restrict__ score_w, const float* __restrict__ score_b,
           float* __restrict__ other)
{
    extern __shared__ float smf[];
    float* As = smf;
    float* Bs = smf + 2 * S2_TILE;

    const int tid = threadIdx.x;
    const int lane = tid & 31;
    const int wid = tid >> 5;
    const int wm = wid >> 2;
    const int wn = wid & 3;
    const int q0 = blockIdx.y * 128;
    const int c0 = blockIdx.x * 128;

    const int lq = lane >> 2;
    const int ld = lane & 3;

    float sacc[4][4][4];
#pragma unroll
    for (int mi = 0; mi < 4; mi++)
#pragma unroll
        for (int ni = 0; ni < 4; ni++)
#pragma unroll
            for (int r = 0; r < 4; r++) sacc[mi][ni][r] = 0.0f;

    for (int k = 0; k < 8; k++) {
        float macc[4][4][4];
#pragma unroll
        for (int mi = 0; mi < 4; mi++)
#pragma unroll
            for (int ni = 0; ni < 4; ni++)
#pragma unroll
                for (int r = 0; r < 4; r++) macc[mi][ni][r] = 0.0f;

        s2_load(As, Bs, qtf, Tk, q0, c0, tid, k, 0, 0);

        for (int t = 0; t < 16; t++) {
            const int buf = t & 1;
            if (t < 15) {
                s2_load(As, Bs, qtf, Tk, q0, c0, tid, k, t + 1, buf ^ 1);
                asm volatile("cp.async.wait_group 1;" ::: "memory");
            } else {
                asm volatile("cp.async.wait_group 0;" ::: "memory");
            }
            __syncthreads();

            const float* pa = As + buf * S2_TILE;
            const float* pb = Bs + buf * S2_TILE;
#pragma unroll
            for (int d8 = 0; d8 < 4; d8++) {
                float a[4][4], b[4][2];
#pragma unroll
                for (int mi = 0; mi < 4; mi++) {
                    const float* p = pa + (wm * 64 + mi * 16 + lq) * S2_ROWPAD + d8 * 8 + ld;
                    a[mi][0] = p[0];
                    a[mi][1] = p[8 * S2_ROWPAD];
                    a[mi][2] = p[4];
                    a[mi][3] = p[8 * S2_ROWPAD + 4];
                }
#pragma unroll
                for (int ni = 0; ni < 4; ni++) {
                    const float* p = pb + (wn * 32 + ni * 8 + lq) * S2_ROWPAD + d8 * 8 + ld;
                    b[ni][0] = p[0];
                    b[ni][1] = p[4];
                }
#pragma unroll
                for (int mi = 0; mi < 4; mi++)
#pragma unroll
                    for (int ni = 0; ni < 4; ni++)
                        mma_tf32(macc[mi][ni], a[mi], b[ni]);
            }
            __syncthreads();
        }

        const float w = __ldg(score_w + k);
#pragma unroll
        for (int mi = 0; mi < 4; mi++)
#pragma unroll
            for (int ni = 0; ni < 4; ni++)
#pragma unroll
                for (int r = 0; r < 4; r++)
                    sacc[mi][ni][r] = fmaf(fmaxf(macc[mi][ni][r], 0.0f), w, sacc[mi][ni][r]);
    }

    const float sb = __ldg(score_b);
#pragma unroll
    for (int mi = 0; mi < 4; mi++) {
        const int q = q0 + wm * 64 + mi * 16 + lq;
#pragma unroll
        for (int ni = 0; ni < 4; ni++) {
            const int c = c0 + wn * 32 + ni * 8 + 2 * ld;
            float2 v0 = make_float2(sb + sacc[mi][ni][0], sb + sacc[mi][ni][1]);
            float2 v1 = make_float2(sb + sacc[mi][ni][2], sb + sacc[mi][ni][3]);
            *(float2*)(other + (size_t)q * 4096 + c) = v0;
            *(float2*)(other + (size_t)(q + 8) * 4096 + c) = v1;
        }
    }
}

// ---------------------------------------------------------------------------
__global__ void softmax_rows(float* __restrict__ o)
{
    const int row = blockIdx.x;
    float* p = o + (size_t)row * 4096;
    const int tid = threadIdx.x;

    float v[16];
    float mx = -1e30f;
#pragma unroll
    for (int i = 0; i < 16; i++) {
        v[i] = p[tid + (i << 8)];
        mx = fmaxf(mx, v[i]);
    }
    __shared__ float sm[8];
#pragma unroll
    for (int o2 = 16; o2 > 0; o2 >>= 1)
        mx = fmaxf(mx, __shfl_xor_sync(0xffffffffu, mx, o2));
    if ((tid & 31) == 0) sm[tid >> 5] = mx;
    __syncthreads();
    mx = sm[0];
#pragma unroll
    for (int i = 1; i < 8; i++) mx = fmaxf(mx, sm[i]);
    __syncthreads();

    float s = 0.0f;
#pragma unroll
    for (int i = 0; i < 16; i++) { v[i] = expf(v[i] - mx); s += v[i]; }
#pragma unroll
    for (int o2 = 16; o2 > 0; o2 >>= 1)
        s += __shfl_xor_sync(0xffffffffu, s, o2);
    if ((tid & 31) == 0) sm[tid >> 5] = s;
    __syncthreads();
    s = 0.0f;
#pragma unroll
    for (int i = 0; i < 8; i++) s += sm[i];
    float inv = 1.0f / s;
#pragma unroll
    for (int i = 0; i < 16; i++) p[tid + (i << 8)] = v[i] * inv;
}

// ---------------------------------------------------------------------------
// Prep kernels
// ---------------------------------------------------------------------------
__global__ void transpose_hw(const float* __restrict__ hw)
{
    int idx = blockIdx.x * blockDim.x + threadIdx.x;
    int l = idx >> 9;
    int d = idx & 511;
    g_hwT[d * 64 + l] = hw[idx];
}

__global__ void round_query(const float* __restrict__ q)
{
    int idx = blockIdx.x * blockDim.x + threadIdx.x;
    g_qtf[idx] = tf32r(q[idx]);
}

// in [R][C] -> ohi/olo [C][R] with hi/lo tf32 split. block (32,8), grid (C/32, R/32)
__global__ void transpose_split(const float* __restrict__ in,
                                float* __restrict__ ohi, float* __restrict__ olo,
                                int R, int C)
{
    __shared__ float t[32][33];
    const int c0 = blockIdx.x * 32;
    const int r0 = blockIdx.y * 32;
    const int tx = threadIdx.x, ty = threadIdx.y;
#pragma unroll
    for (int i = ty; i < 32; i += 8)
        t[i][tx] = in[(size_t)(r0 + i) * C + c0 + tx];
    __syncthreads();
#pragma unroll
    for (int i = ty; i < 32; i += 8) {
        float v = t[tx][i];
        float hi = tf32r(v);
        size_t o = (size_t)(c0 + i) * R + r0 + tx;
        ohi[o] = hi;
        olo[o] = tf32r(v - hi);
    }
}

// qf = query + sum_z qfp[z]
__global__ void reduce_qf(const float* __restrict__ query)
{
    size_t idx = (size_t)blockIdx.x * blockDim.x + threadIdx.x;  // 0..2097151
    const size_t S = (size_t)4096 * 512;
    g_qf[idx] = query[idx] + g_qfp[idx] + g_qfp[idx + S] +
                g_qfp[idx + 2 * S] + g_qfp[idx + 3 * S];
}

// ---------------------------------------------------------------------------
extern "C" void kernel_launch(void* const* d_in, const int* in_sizes, int n_in,
                              void* d_out, int out_size)
{
    const float* class_v = (const float*)d_in[0];
    const float* query_v = (const float*)d_in[1];
    const float* Mmat    = (const float*)d_in[2];
    const float* score_w = (const float*)d_in[3];
    const float* score_b = (const float*)d_in[4];
    const float* hash_w  = (const float*)d_in[5];
    const float* hash_b  = (const float*)d_in[6];
    float* out = (float*)d_out;

    float *T, *other, *qf, *hwT, *qtf, *mth, *mtl, *cth, *ctl, *qfp;
    cudaGetSymbolAddress((void**)&T, g_T);
    cudaGetSymbolAddress((void**)&other, g_other);
    cudaGetSymbolAddress((void**)&qf, g_qf);
    cudaGetSymbolAddress((void**)&hwT, g_hwT);
    cudaGetSymbolAddress((void**)&qtf, g_qtf);
    cudaGetSymbolAddress((void**)&mth, g_MT_hi);
    cudaGetSymbolAddress((void**)&mtl, g_MT_lo);
    cudaGetSymbolAddress((void**)&cth, g_clT_hi);
    cudaGetSymbolAddress((void**)&ctl, g_clT_lo);
    cudaGetSymbolAddress((void**)&qfp, g_qfp);

    cudaFuncSetAttribute(stage2_mma, cudaFuncAttributeMaxDynamicSharedMemorySize, S2_SMEM);
    cudaFuncSetAttribute(gemm3x<0>, cudaFuncAttributeMaxDynamicSharedMemorySize, G3_SMEM);
    cudaFuncSetAttribute(gemm3x<1>, cudaFuncAttributeMaxDynamicSharedMemorySize, G3_SMEM);

    // prep
    transpose_hw<<<128, 256>>>(hash_w);
    round_query<<<8192, 256>>>(query_v);
    transpose_split<<<dim3(128, 16), dim3(32, 8)>>>(Mmat, mth, mtl, 512, 4096);
    transpose_split<<<dim3(16, 128), dim3(32, 8)>>>(class_v, cth, ctl, 4096, 512);

    // Stage 1: Tk = class @ M (3xTF32, scatter epilogue)
    gemm3x<0><<<dim3(32, 32, 1), 256, G3_SMEM>>>(class_v, mth, mtl, T, 512, 512, 512);

    // Stage 2: fused bilinear + relu + score
    stage2_mma<<<dim3(32, 32), 256, S2_SMEM>>>(qtf, T, score_w, score_b, other);

    // Stage 3: softmax
    softmax_rows<<<4096, 256>>>(other);

    // Stage 4: qf partials = scores @ class (3xTF32, split-K=4), then reduce + residual
    gemm3x<1><<<dim3(4, 32, 4), 256, G3_SMEM>>>(other, cth, ctl, qfp, 4096, 4096, 1024);
    reduce_qf<<<8192, 256>>>(query_v);

    // Stage 5: out = tanh(qf @ hwT + hash_b)
    gemm_f32<64, 64, 16, 4, 4, 2><<<dim3(1, 64), 256>>>(
        qf, hwT, hash_b, out, 4096, 64, 512);
}